// round 9
// baseline (speedup 1.0000x reference)
#include <cuda_runtime.h>
#include <cuda_bf16.h>
#include <cstdint>

#define NTOK 49
#define CDIM 128
#define HEADS 4
#define HD 32
#define THREADS 768

static constexpr float SCALE = 0.17677669529663687f; // 32^-0.5

typedef unsigned long long ull;
typedef unsigned int u32;
typedef unsigned short u16;

// ---- smem byte offsets ----
#define OFF_AH   0u         // A-fragment tile hi: 64 rows x 128 k bf16 = 16KB
#define OFF_AL   16384u     // A-fragment tile lo: 16KB
#define OFF_QKV  32768u     // fp32 qkv [49][404] = 79184B
#define OFF_MASK 111952u    // 49*49 fp32 = 9604B
#define OFF_P    121568u    // p-scratch [49][196] fp32 = 38416B
#define SMEM_BYTES 160000
#define QKV_STR  404

// ---- device globals: fragment-ordered bf16 hi/lo weights + gathered pos bias ----
__device__ u32 g_wq_hi[48 * 8 * 32 * 2];   // [nt][kc][lane][reg] u32; nt 0-47 (3 chunks x 16)
__device__ u32 g_wq_lo[48 * 8 * 32 * 2];
__device__ u32 g_wp_hi[16 * 8 * 32 * 2];
__device__ u32 g_wp_lo[16 * 8 * 32 * 2];
__device__ float g_pbias[HEADS * NTOK * NTOK];

// ============================ helpers ============================
__device__ __forceinline__ ull pk2(float lo, float hi) {
    ull r; asm("mov.b64 %0, {%1, %2};" : "=l"(r) : "f"(lo), "f"(hi)); return r;
}
__device__ __forceinline__ void upk2(ull v, float& lo, float& hi) {
    asm("mov.b64 {%0, %1}, %2;" : "=f"(lo), "=f"(hi) : "l"(v));
}
__device__ __forceinline__ ull fma2(ull a, ull b, ull c) {
    ull d; asm("fma.rn.f32x2 %0, %1, %2, %3;" : "=l"(d) : "l"(a), "l"(b), "l"(c)); return d;
}
__device__ __forceinline__ u32 bf2(float a, float b) {
    __nv_bfloat162 h = __floats2bfloat162_rn(a, b);
    return *reinterpret_cast<u32*>(&h);
}
// A-fragment u32 index for element pair (row, col) with col even, 64x128 tile
__device__ __forceinline__ int a_idx(int row, int col) {
    int mt = row >> 4, rlo = row & 15, kc = col >> 4, kk = col & 15;
    int l = (rlo & 7) * 4 + ((kk & 7) >> 1);
    int reg = ((rlo >> 3) & 1) + (((kk >> 3) & 1) << 1);
    return ((mt * 8 + kc) * 32 + l) * 4 + reg;
}
__device__ __forceinline__ void mma16816(float c[4], const uint4& a, const uint2& b) {
    asm volatile(
        "mma.sync.aligned.m16n8k16.row.col.f32.bf16.bf16.f32 "
        "{%0,%1,%2,%3}, {%4,%5,%6,%7}, {%8,%9}, {%0,%1,%2,%3};"
        : "+f"(c[0]), "+f"(c[1]), "+f"(c[2]), "+f"(c[3])
        : "r"(a.x), "r"(a.y), "r"(a.z), "r"(a.w), "r"(b.x), "r"(b.y));
}

// ================= prep: weights -> bf16 hi/lo fragment order; pos bias gather =================
__global__ void prep_kernel(const float* __restrict__ qkv_w,
                            const float* __restrict__ proj_w,
                            const float* __restrict__ table,
                            const int*   __restrict__ pidx)
{
    int i = blockIdx.x * 256 + threadIdx.x;
    if (i < 3 * CDIM * CDIM) {
        int o = i / CDIM, c = i % CDIM;
        float w = qkv_w[i];
        __nv_bfloat16 h = __float2bfloat16(w);
        float hf = __bfloat162float(h);
        int nt = o >> 3, g = o & 7, kc = c >> 4, kk = c & 15;
        int l = g * 4 + ((kk & 7) >> 1);
        int reg = (kk >> 3) & 1;
        int u16idx = (((nt * 8 + kc) * 32 + l) * 2 + reg) * 2 + (kk & 1);
        ((u16*)g_wq_hi)[u16idx] = *(u16*)&h;
        __nv_bfloat16 lo = __float2bfloat16(w - hf);
        ((u16*)g_wq_lo)[u16idx] = *(u16*)&lo;
    }
    if (i < CDIM * CDIM) {
        int o = i / CDIM, c = i % CDIM;
        float w = proj_w[i];
        __nv_bfloat16 h = __float2bfloat16(w);
        float hf = __bfloat162float(h);
        int nt = o >> 3, g = o & 7, kc = c >> 4, kk = c & 15;
        int l = g * 4 + ((kk & 7) >> 1);
        int reg = (kk >> 3) & 1;
        int u16idx = (((nt * 8 + kc) * 32 + l) * 2 + reg) * 2 + (kk & 1);
        ((u16*)g_wp_hi)[u16idx] = *(u16*)&h;
        __nv_bfloat16 lo = __float2bfloat16(w - hf);
        ((u16*)g_wp_lo)[u16idx] = *(u16*)&lo;
    }
    if (i < HEADS * NTOK * NTOK) {
        int h = i / (NTOK * NTOK), r = i % (NTOK * NTOK);
        int m = r / NTOK, n = r % NTOK;
        g_pbias[i] = table[pidx[n * NTOK + m] * HEADS + h];
    }
}

// ================================ main kernel ================================
__global__ void __launch_bounds__(THREADS, 1)
win_attn_kernel(const float* __restrict__ x,
                const float* __restrict__ mask,
                const float* __restrict__ proj_b,
                float* __restrict__ out,
                int nW)
{
    extern __shared__ char smem[];
    const int b = blockIdx.x;
    const int t = threadIdx.x;
    const int wid = t >> 5;
    const int lane = t & 31;

    u32* sAh = (u32*)(smem + OFF_AH);
    u32* sAl = (u32*)(smem + OFF_AL);
    float* s_qkv  = (float*)(smem + OFF_QKV);
    float* s_mask = (float*)(smem + OFF_MASK);
    float* s_p    = (float*)(smem + OFF_P);

    // ---- Phase 0: zero A-fragment region (padding rows 49-63 must stay 0) ----
    {
        uint4* z = (uint4*)(smem + OFF_AH);
        #pragma unroll 1
        for (int i = t; i < 2048; i += THREADS)
            z[i] = make_uint4(0, 0, 0, 0);
    }
    __syncthreads();

    // ---- Phase 1: x -> A-fragments (hi/lo); mask -> smem ----
    {
        const float4* x4 = (const float4*)(x + (size_t)b * NTOK * CDIM);
        #pragma unroll 1
        for (int i = t; i < NTOK * CDIM / 4; i += THREADS) {
            float4 v = __ldg(x4 + i);
            int n = i >> 5, c4 = (i & 31) << 2;
            float h0 = __bfloat162float(__float2bfloat16(v.x));
            float h1 = __bfloat162float(__float2bfloat16(v.y));
            float h2 = __bfloat162float(__float2bfloat16(v.z));
            float h3 = __bfloat162float(__float2bfloat16(v.w));
            int i0 = a_idx(n, c4);
            int i1 = i0 + 4;
            sAh[i0] = bf2(v.x, v.y);
            sAh[i1] = bf2(v.z, v.w);
            sAl[i0] = bf2(v.x - h0, v.y - h1);
            sAl[i1] = bf2(v.z - h2, v.w - h3);
        }
        const float* mrow = mask + (size_t)(b % nW) * NTOK * NTOK;
        #pragma unroll 1
        for (int i = t; i < NTOK * NTOK; i += THREADS)
            s_mask[i] = __ldg(mrow + i);
    }
    __syncthreads();

    // ---- GEMM1: qkv = x @ Wqkv^T; 24 warps = 3 chunks x (2 mtg x 4 ng) ----
    {
        const int wchunk = wid >> 3;          // 0..2
        const int sub    = wid & 7;
        const int mtg    = sub >> 2;          // 0..1 -> m-tiles {2mtg, 2mtg+1}
        const int ng     = sub & 3;           // 0..3 -> n-tiles ng*4..ng*4+3

        float C[2][4][4];
        #pragma unroll
        for (int a = 0; a < 2; a++)
            #pragma unroll
            for (int j = 0; j < 4; j++)
                C[a][j][0] = C[a][j][1] = C[a][j][2] = C[a][j][3] = 0.f;

        #pragma unroll
        for (int kc = 0; kc < 8; kc++) {
            uint4 ah0 = *(const uint4*)(sAh + (((2 * mtg)     * 8 + kc) * 32 + lane) * 4);
            uint4 al0 = *(const uint4*)(sAl + (((2 * mtg)     * 8 + kc) * 32 + lane) * 4);
            uint4 ah1 = *(const uint4*)(sAh + (((2 * mtg + 1) * 8 + kc) * 32 + lane) * 4);
            uint4 al1 = *(const uint4*)(sAl + (((2 * mtg + 1) * 8 + kc) * 32 + lane) * 4);
            #pragma unroll
            for (int j = 0; j < 4; j++) {
                int ntg = wchunk * 16 + ng * 4 + j;
                int bidx = ((ntg * 8 + kc) * 32 + lane) * 2;
                uint2 bh = __ldg((const uint2*)(g_wq_hi + bidx));
                uint2 bl = __ldg((const uint2*)(g_wq_lo + bidx));
                mma16816(C[0][j], ah0, bh);
                mma16816(C[0][j], ah0, bl);
                mma16816(C[0][j], al0, bh);
                mma16816(C[1][j], ah1, bh);
                mma16816(C[1][j], ah1, bl);
                mma16816(C[1][j], al1, bh);
            }
        }
        // store C -> s_qkv fp32
        int g = lane >> 2, t4 = lane & 3;
        #pragma unroll
        for (int a = 0; a < 2; a++) {
            int row0 = (2 * mtg + a) * 16 + g;
            #pragma unroll
            for (int j = 0; j < 4; j++) {
                int col = wchunk * 128 + (ng * 4 + j) * 8 + 2 * t4;
                if (row0 < NTOK)
                    *(float2*)(s_qkv + row0 * QKV_STR + col) = make_float2(C[a][j][0], C[a][j][1]);
                if (row0 + 8 < NTOK)
                    *(float2*)(s_qkv + (row0 + 8) * QKV_STR + col) = make_float2(C[a][j][2], C[a][j][3]);
            }
        }
    }
    __syncthreads();

    // ---- Phase 3: scalar attention per (head, row); logits in p-scratch ----
    if (t < HEADS * NTOK) {
        const int hh = t / NTOK;
        const int nn = t % NTOK;

        ull q2[16];
        const ulonglong2* qrow = (const ulonglong2*)(s_qkv + nn * QKV_STR + hh * HD);
        #pragma unroll
        for (int i = 0; i < 8; i++) {
            ulonglong2 v = qrow[i];
            q2[2 * i] = v.x; q2[2 * i + 1] = v.y;
        }
        float mx = -1e30f;
        const float* pbrow = g_pbias + hh * (NTOK * NTOK) + nn;
        const float* mkrow = s_mask + nn * NTOK;
        float* pcol = s_p + t;                 // private column, stride 196

        #pragma unroll
        for (int m = 0; m < NTOK; m++) {
            const ulonglong2* krow =
                (const ulonglong2*)(s_qkv + m * QKV_STR + CDIM + hh * HD);
            ull sa = 0ull, sb = 0ull;
            #pragma unroll
            for (int i = 0; i < 8; i++) {
                ulonglong2 kv = krow[i];
                sa = fma2(q2[2 * i],     kv.x, sa);
                sb = fma2(q2[2 * i + 1], kv.y, sb);
            }
            float a0, a1, b0, b1; upk2(sa, a0, a1); upk2(sb, b0, b1);
            float dot = (a0 + a1) + (b0 + b1);
            float s = fmaf(dot, SCALE, __ldg(pbrow + m * NTOK) + mkrow[m]);
            pcol[m * 196] = s;
            mx = fmaxf(mx, s);
        }
        ull oacc[16];
        #pragma unroll
        for (int i = 0; i < 16; i++) oacc[i] = 0ull;
        float sum = 0.f;
        #pragma unroll
        for (int m = 0; m < NTOK; m++) {
            float e = __expf(pcol[m * 196] - mx);
            sum += e;
            ull e2 = pk2(e, e);
            const ulonglong2* vrow =
                (const ulonglong2*)(s_qkv + m * QKV_STR + 2 * CDIM + hh * HD);
            #pragma unroll
            for (int i = 0; i < 8; i++) {
                ulonglong2 vv = vrow[i];
                oacc[2 * i]     = fma2(e2, vv.x, oacc[2 * i]);
                oacc[2 * i + 1] = fma2(e2, vv.y, oacc[2 * i + 1]);
            }
        }
        float inv = 1.0f / sum;

        // write o -> A-fragments (hi/lo); rows 49-63 keep zeros (x frags are dead:
        // all GEMM1 reads completed before the preceding __syncthreads)
        #pragma unroll
        for (int i = 0; i < 16; i++) {
            float v0, v1; upk2(oacc[i], v0, v1);
            v0 *= inv; v1 *= inv;
            float h0 = __bfloat162float(__float2bfloat16(v0));
            float h1 = __bfloat162float(__float2bfloat16(v1));
            int c = hh * HD + 2 * i;
            int idx = a_idx(nn, c);
            sAh[idx] = bf2(v0, v1);
            sAl[idx] = bf2(v0 - h0, v1 - h1);
        }
    }
    __syncthreads();

    // ---- GEMM2: out = o @ Wproj^T + bias; 8 warps (2 mtg x 4 ng) ----
    if (wid < 8) {
        const int mtg = (wid >> 2) & 1;
        const int ng  = wid & 3;

        float C[2][4][4];
        #pragma unroll
        for (int a = 0; a < 2; a++)
            #pragma unroll
            for (int j = 0; j < 4; j++)
                C[a][j][0] = C[a][j][1] = C[a][j][2] = C[a][j][3] = 0.f;

        #pragma unroll
        for (int kc = 0; kc < 8; kc++) {
            uint4 ah0 = *(const uint4*)(sAh + (((2 * mtg)     * 8 + kc) * 32 + lane) * 4);
            uint4 al0 = *(const uint4*)(sAl + (((2 * mtg)     * 8 + kc) * 32 + lane) * 4);
            uint4 ah1 = *(const uint4*)(sAh + (((2 * mtg + 1) * 8 + kc) * 32 + lane) * 4);
            uint4 al1 = *(const uint4*)(sAl + (((2 * mtg + 1) * 8 + kc) * 32 + lane) * 4);
            #pragma unroll
            for (int j = 0; j < 4; j++) {
                int ntg = ng * 4 + j;
                int bidx = ((ntg * 8 + kc) * 32 + lane) * 2;
                uint2 bh = __ldg((const uint2*)(g_wp_hi + bidx));
                uint2 bl = __ldg((const uint2*)(g_wp_lo + bidx));
                mma16816(C[0][j], ah0, bh);
                mma16816(C[0][j], ah0, bl);
                mma16816(C[0][j], al0, bh);
                mma16816(C[1][j], ah1, bh);
                mma16816(C[1][j], ah1, bl);
                mma16816(C[1][j], al1, bh);
            }
        }
        int g = lane >> 2, t4 = lane & 3;
        float* ob = out + (size_t)b * NTOK * CDIM;
        #pragma unroll
        for (int a = 0; a < 2; a++) {
            int row0 = (2 * mtg + a) * 16 + g;
            #pragma unroll
            for (int j = 0; j < 4; j++) {
                int col = (ng * 4 + j) * 8 + 2 * t4;
                float2 bias = __ldg((const float2*)(proj_b + col));
                if (row0 < NTOK)
                    *(float2*)(ob + row0 * CDIM + col) =
                        make_float2(C[a][j][0] + bias.x, C[a][j][1] + bias.y);
                if (row0 + 8 < NTOK)
                    *(float2*)(ob + (row0 + 8) * CDIM + col) =
                        make_float2(C[a][j][2] + bias.x, C[a][j][3] + bias.y);
            }
        }
    }
}

extern "C" void kernel_launch(void* const* d_in, const int* in_sizes, int n_in,
                              void* d_out, int out_size)
{
    const float* x      = (const float*)d_in[0];
    const float* qkv_w  = (const float*)d_in[1];
    const float* proj_w = (const float*)d_in[2];
    const float* proj_b = (const float*)d_in[3];
    const float* table  = (const float*)d_in[4];
    const float* mask   = (const float*)d_in[5];
    const int*   pidx   = (const int*)d_in[6];
    float* out = (float*)d_out;

    int B  = in_sizes[0] / (NTOK * CDIM);      // 8192
    int nW = in_sizes[5] / (NTOK * NTOK);      // 1024

    prep_kernel<<<(3 * CDIM * CDIM + 255) / 256, 256>>>(qkv_w, proj_w, table, pidx);

    cudaFuncSetAttribute(win_attn_kernel,
                         cudaFuncAttributeMaxDynamicSharedMemorySize, SMEM_BYTES);
    win_attn_kernel<<<B, THREADS, SMEM_BYTES>>>(x, mask, proj_b, out, nW);
}

// round 10
// speedup vs baseline: 1.0007x; 1.0007x over previous
#include <cuda_runtime.h>
#include <cuda_bf16.h>
#include <cstdint>

#define NTOK 49
#define CDIM 128
#define HEADS 4
#define HD 32
#define THREADS 768

static constexpr float SCALE = 0.17677669529663687f; // 32^-0.5

typedef unsigned long long ull;
typedef unsigned int u32;
typedef unsigned short u16;

// ---- smem byte offsets ----
#define OFF_AH   0u         // A-fragment tile hi: 64 rows x 128 k bf16 = 16KB
#define OFF_AL   16384u     // A-fragment tile lo: 16KB
#define OFF_QKV  32768u     // fp32 qkv [49][404] = 79184B
#define OFF_MASK 111952u    // 49*49 fp32 = 9604B
#define OFF_P    121568u    // p-scratch [49][196] fp32 = 38416B
#define SMEM_BYTES 160000
#define QKV_STR  404

// ---- device globals: fragment-ordered bf16 hi/lo weights + gathered pos bias ----
__device__ u32 g_wq_hi[48 * 8 * 32 * 2];   // [nt][kc][lane][reg] u32; nt 0-47 (3 chunks x 16)
__device__ u32 g_wq_lo[48 * 8 * 32 * 2];
__device__ u32 g_wp_hi[16 * 8 * 32 * 2];
__device__ u32 g_wp_lo[16 * 8 * 32 * 2];
__device__ float g_pbias[HEADS * NTOK * NTOK];

// ============================ helpers ============================
__device__ __forceinline__ ull pk2(float lo, float hi) {
    ull r; asm("mov.b64 %0, {%1, %2};" : "=l"(r) : "f"(lo), "f"(hi)); return r;
}
__device__ __forceinline__ void upk2(ull v, float& lo, float& hi) {
    asm("mov.b64 {%0, %1}, %2;" : "=f"(lo), "=f"(hi) : "l"(v));
}
__device__ __forceinline__ ull fma2(ull a, ull b, ull c) {
    ull d; asm("fma.rn.f32x2 %0, %1, %2, %3;" : "=l"(d) : "l"(a), "l"(b), "l"(c)); return d;
}
__device__ __forceinline__ u32 bf2(float a, float b) {
    __nv_bfloat162 h = __floats2bfloat162_rn(a, b);
    return *reinterpret_cast<u32*>(&h);
}
// A-fragment u32 index for element pair (row, col) with col even, 64x128 tile
__device__ __forceinline__ int a_idx(int row, int col) {
    int mt = row >> 4, rlo = row & 15, kc = col >> 4, kk = col & 15;
    int l = (rlo & 7) * 4 + ((kk & 7) >> 1);
    int reg = ((rlo >> 3) & 1) + (((kk >> 3) & 1) << 1);
    return ((mt * 8 + kc) * 32 + l) * 4 + reg;
}
__device__ __forceinline__ void mma16816(float c[4], const uint4& a, const uint2& b) {
    asm volatile(
        "mma.sync.aligned.m16n8k16.row.col.f32.bf16.bf16.f32 "
        "{%0,%1,%2,%3}, {%4,%5,%6,%7}, {%8,%9}, {%0,%1,%2,%3};"
        : "+f"(c[0]), "+f"(c[1]), "+f"(c[2]), "+f"(c[3])
        : "r"(a.x), "r"(a.y), "r"(a.z), "r"(a.w), "r"(b.x), "r"(b.y));
}

// ================= prep: weights -> bf16 hi/lo fragment order; pos bias gather =================
__global__ void prep_kernel(const float* __restrict__ qkv_w,
                            const float* __restrict__ proj_w,
                            const float* __restrict__ table,
                            const int*   __restrict__ pidx)
{
    int i = blockIdx.x * 256 + threadIdx.x;
    if (i < 3 * CDIM * CDIM) {
        int o = i / CDIM, c = i % CDIM;
        float w = qkv_w[i];
        __nv_bfloat16 h = __float2bfloat16(w);
        float hf = __bfloat162float(h);
        int nt = o >> 3, g = o & 7, kc = c >> 4, kk = c & 15;
        int l = g * 4 + ((kk & 7) >> 1);
        int reg = (kk >> 3) & 1;
        int u16idx = (((nt * 8 + kc) * 32 + l) * 2 + reg) * 2 + (kk & 1);
        ((u16*)g_wq_hi)[u16idx] = *(u16*)&h;
        __nv_bfloat16 lo = __float2bfloat16(w - hf);
        ((u16*)g_wq_lo)[u16idx] = *(u16*)&lo;
    }
    if (i < CDIM * CDIM) {
        int o = i / CDIM, c = i % CDIM;
        float w = proj_w[i];
        __nv_bfloat16 h = __float2bfloat16(w);
        float hf = __bfloat162float(h);
        int nt = o >> 3, g = o & 7, kc = c >> 4, kk = c & 15;
        int l = g * 4 + ((kk & 7) >> 1);
        int reg = (kk >> 3) & 1;
        int u16idx = (((nt * 8 + kc) * 32 + l) * 2 + reg) * 2 + (kk & 1);
        ((u16*)g_wp_hi)[u16idx] = *(u16*)&h;
        __nv_bfloat16 lo = __float2bfloat16(w - hf);
        ((u16*)g_wp_lo)[u16idx] = *(u16*)&lo;
    }
    if (i < HEADS * NTOK * NTOK) {
        int h = i / (NTOK * NTOK), r = i % (NTOK * NTOK);
        int m = r / NTOK, n = r % NTOK;
        g_pbias[i] = table[pidx[n * NTOK + m] * HEADS + h];
    }
}

// ================================ main kernel ================================
__global__ void __launch_bounds__(THREADS, 1)
win_attn_kernel(const float* __restrict__ x,
                const float* __restrict__ mask,
                const float* __restrict__ proj_b,
                float* __restrict__ out,
                int nW)
{
    extern __shared__ char smem[];
    const int b = blockIdx.x;
    const int t = threadIdx.x;
    const int wid = t >> 5;
    const int lane = t & 31;

    u32* sAh = (u32*)(smem + OFF_AH);
    u32* sAl = (u32*)(smem + OFF_AL);
    float* s_qkv  = (float*)(smem + OFF_QKV);
    float* s_mask = (float*)(smem + OFF_MASK);
    float* s_p    = (float*)(smem + OFF_P);

    // ---- Phase 0: zero A-fragment region (padding rows 49-63 must stay 0) ----
    {
        uint4* z = (uint4*)(smem + OFF_AH);
        #pragma unroll 1
        for (int i = t; i < 2048; i += THREADS)
            z[i] = make_uint4(0, 0, 0, 0);
    }
    __syncthreads();

    // ---- Phase 1: x -> A-fragments (hi/lo); mask -> smem ----
    {
        const float4* x4 = (const float4*)(x + (size_t)b * NTOK * CDIM);
        #pragma unroll 1
        for (int i = t; i < NTOK * CDIM / 4; i += THREADS) {
            float4 v = __ldg(x4 + i);
            int n = i >> 5, c4 = (i & 31) << 2;
            float h0 = __bfloat162float(__float2bfloat16(v.x));
            float h1 = __bfloat162float(__float2bfloat16(v.y));
            float h2 = __bfloat162float(__float2bfloat16(v.z));
            float h3 = __bfloat162float(__float2bfloat16(v.w));
            int i0 = a_idx(n, c4);
            int i1 = i0 + 4;
            sAh[i0] = bf2(v.x, v.y);
            sAh[i1] = bf2(v.z, v.w);
            sAl[i0] = bf2(v.x - h0, v.y - h1);
            sAl[i1] = bf2(v.z - h2, v.w - h3);
        }
        const float* mrow = mask + (size_t)(b % nW) * NTOK * NTOK;
        #pragma unroll 1
        for (int i = t; i < NTOK * NTOK; i += THREADS)
            s_mask[i] = __ldg(mrow + i);
    }
    __syncthreads();

    // ---- GEMM1: qkv = x @ Wqkv^T; 24 warps = 3 chunks x (2 mtg x 4 ng) ----
    {
        const int wchunk = wid >> 3;          // 0..2
        const int sub    = wid & 7;
        const int mtg    = sub >> 2;          // 0..1 -> m-tiles {2mtg, 2mtg+1}
        const int ng     = sub & 3;           // 0..3 -> n-tiles ng*4..ng*4+3

        float C[2][4][4];
        #pragma unroll
        for (int a = 0; a < 2; a++)
            #pragma unroll
            for (int j = 0; j < 4; j++)
                C[a][j][0] = C[a][j][1] = C[a][j][2] = C[a][j][3] = 0.f;

        #pragma unroll
        for (int kc = 0; kc < 8; kc++) {
            uint4 ah0 = *(const uint4*)(sAh + (((2 * mtg)     * 8 + kc) * 32 + lane) * 4);
            uint4 al0 = *(const uint4*)(sAl + (((2 * mtg)     * 8 + kc) * 32 + lane) * 4);
            uint4 ah1 = *(const uint4*)(sAh + (((2 * mtg + 1) * 8 + kc) * 32 + lane) * 4);
            uint4 al1 = *(const uint4*)(sAl + (((2 * mtg + 1) * 8 + kc) * 32 + lane) * 4);
            #pragma unroll
            for (int j = 0; j < 4; j++) {
                int ntg = wchunk * 16 + ng * 4 + j;
                int bidx = ((ntg * 8 + kc) * 32 + lane) * 2;
                uint2 bh = __ldg((const uint2*)(g_wq_hi + bidx));
                uint2 bl = __ldg((const uint2*)(g_wq_lo + bidx));
                mma16816(C[0][j], ah0, bh);
                mma16816(C[0][j], ah0, bl);
                mma16816(C[0][j], al0, bh);
                mma16816(C[1][j], ah1, bh);
                mma16816(C[1][j], ah1, bl);
                mma16816(C[1][j], al1, bh);
            }
        }
        // store C -> s_qkv fp32
        int g = lane >> 2, t4 = lane & 3;
        #pragma unroll
        for (int a = 0; a < 2; a++) {
            int row0 = (2 * mtg + a) * 16 + g;
            #pragma unroll
            for (int j = 0; j < 4; j++) {
                int col = wchunk * 128 + (ng * 4 + j) * 8 + 2 * t4;
                if (row0 < NTOK)
                    *(float2*)(s_qkv + row0 * QKV_STR + col) = make_float2(C[a][j][0], C[a][j][1]);
                if (row0 + 8 < NTOK)
                    *(float2*)(s_qkv + (row0 + 8) * QKV_STR + col) = make_float2(C[a][j][2], C[a][j][3]);
            }
        }
    }
    __syncthreads();

    // ---- Phase 3: scalar attention per (head, row); logits in p-scratch ----
    if (t < HEADS * NTOK) {
        const int hh = t / NTOK;
        const int nn = t % NTOK;

        ull q2[16];
        const ulonglong2* qrow = (const ulonglong2*)(s_qkv + nn * QKV_STR + hh * HD);
        #pragma unroll
        for (int i = 0; i < 8; i++) {
            ulonglong2 v = qrow[i];
            q2[2 * i] = v.x; q2[2 * i + 1] = v.y;
        }
        float mx = -1e30f;
        const float* pbrow = g_pbias + hh * (NTOK * NTOK) + nn;
        const float* mkrow = s_mask + nn * NTOK;
        float* pcol = s_p + t;                 // private column, stride 196

        #pragma unroll
        for (int m = 0; m < NTOK; m++) {
            const ulonglong2* krow =
                (const ulonglong2*)(s_qkv + m * QKV_STR + CDIM + hh * HD);
            ull sa = 0ull, sb = 0ull;
            #pragma unroll
            for (int i = 0; i < 8; i++) {
                ulonglong2 kv = krow[i];
                sa = fma2(q2[2 * i],     kv.x, sa);
                sb = fma2(q2[2 * i + 1], kv.y, sb);
            }
            float a0, a1, b0, b1; upk2(sa, a0, a1); upk2(sb, b0, b1);
            float dot = (a0 + a1) + (b0 + b1);
            float s = fmaf(dot, SCALE, __ldg(pbrow + m * NTOK) + mkrow[m]);
            pcol[m * 196] = s;
            mx = fmaxf(mx, s);
        }
        ull oacc[16];
        #pragma unroll
        for (int i = 0; i < 16; i++) oacc[i] = 0ull;
        float sum = 0.f;
        #pragma unroll
        for (int m = 0; m < NTOK; m++) {
            float e = __expf(pcol[m * 196] - mx);
            sum += e;
            ull e2 = pk2(e, e);
            const ulonglong2* vrow =
                (const ulonglong2*)(s_qkv + m * QKV_STR + 2 * CDIM + hh * HD);
            #pragma unroll
            for (int i = 0; i < 8; i++) {
                ulonglong2 vv = vrow[i];
                oacc[2 * i]     = fma2(e2, vv.x, oacc[2 * i]);
                oacc[2 * i + 1] = fma2(e2, vv.y, oacc[2 * i + 1]);
            }
        }
        float inv = 1.0f / sum;

        // write o -> A-fragments (hi/lo); rows 49-63 keep zeros (x frags are dead:
        // all GEMM1 reads completed before the preceding __syncthreads)
        #pragma unroll
        for (int i = 0; i < 16; i++) {
            float v0, v1; upk2(oacc[i], v0, v1);
            v0 *= inv; v1 *= inv;
            float h0 = __bfloat162float(__float2bfloat16(v0));
            float h1 = __bfloat162float(__float2bfloat16(v1));
            int c = hh * HD + 2 * i;
            int idx = a_idx(nn, c);
            sAh[idx] = bf2(v0, v1);
            sAl[idx] = bf2(v0 - h0, v1 - h1);
        }
    }
    __syncthreads();

    // ---- GEMM2: out = o @ Wproj^T + bias; 8 warps (2 mtg x 4 ng) ----
    if (wid < 8) {
        const int mtg = (wid >> 2) & 1;
        const int ng  = wid & 3;

        float C[2][4][4];
        #pragma unroll
        for (int a = 0; a < 2; a++)
            #pragma unroll
            for (int j = 0; j < 4; j++)
                C[a][j][0] = C[a][j][1] = C[a][j][2] = C[a][j][3] = 0.f;

        #pragma unroll
        for (int kc = 0; kc < 8; kc++) {
            uint4 ah0 = *(const uint4*)(sAh + (((2 * mtg)     * 8 + kc) * 32 + lane) * 4);
            uint4 al0 = *(const uint4*)(sAl + (((2 * mtg)     * 8 + kc) * 32 + lane) * 4);
            uint4 ah1 = *(const uint4*)(sAh + (((2 * mtg + 1) * 8 + kc) * 32 + lane) * 4);
            uint4 al1 = *(const uint4*)(sAl + (((2 * mtg + 1) * 8 + kc) * 32 + lane) * 4);
            #pragma unroll
            for (int j = 0; j < 4; j++) {
                int ntg = ng * 4 + j;
                int bidx = ((ntg * 8 + kc) * 32 + lane) * 2;
                uint2 bh = __ldg((const uint2*)(g_wp_hi + bidx));
                uint2 bl = __ldg((const uint2*)(g_wp_lo + bidx));
                mma16816(C[0][j], ah0, bh);
                mma16816(C[0][j], ah0, bl);
                mma16816(C[0][j], al0, bh);
                mma16816(C[1][j], ah1, bh);
                mma16816(C[1][j], ah1, bl);
                mma16816(C[1][j], al1, bh);
            }
        }
        int g = lane >> 2, t4 = lane & 3;
        float* ob = out + (size_t)b * NTOK * CDIM;
        #pragma unroll
        for (int a = 0; a < 2; a++) {
            int row0 = (2 * mtg + a) * 16 + g;
            #pragma unroll
            for (int j = 0; j < 4; j++) {
                int col = (ng * 4 + j) * 8 + 2 * t4;
                float2 bias = __ldg((const float2*)(proj_b + col));
                if (row0 < NTOK)
                    *(float2*)(ob + row0 * CDIM + col) =
                        make_float2(C[a][j][0] + bias.x, C[a][j][1] + bias.y);
                if (row0 + 8 < NTOK)
                    *(float2*)(ob + (row0 + 8) * CDIM + col) =
                        make_float2(C[a][j][2] + bias.x, C[a][j][3] + bias.y);
            }
        }
    }
}

extern "C" void kernel_launch(void* const* d_in, const int* in_sizes, int n_in,
                              void* d_out, int out_size)
{
    const float* x      = (const float*)d_in[0];
    const float* qkv_w  = (const float*)d_in[1];
    const float* proj_w = (const float*)d_in[2];
    const float* proj_b = (const float*)d_in[3];
    const float* table  = (const float*)d_in[4];
    const float* mask   = (const float*)d_in[5];
    const int*   pidx   = (const int*)d_in[6];
    float* out = (float*)d_out;

    int B  = in_sizes[0] / (NTOK * CDIM);      // 8192
    int nW = in_sizes[5] / (NTOK * NTOK);      // 1024

    prep_kernel<<<(3 * CDIM * CDIM + 255) / 256, 256>>>(qkv_w, proj_w, table, pidx);

    cudaFuncSetAttribute(win_attn_kernel,
                         cudaFuncAttributeMaxDynamicSharedMemorySize, SMEM_BYTES);
    win_attn_kernel<<<B, THREADS, SMEM_BYTES>>>(x, mask, proj_b, out, nW);
}

// round 11
// speedup vs baseline: 1.0026x; 1.0019x over previous
#include <cuda_runtime.h>
#include <cuda_bf16.h>
#include <cstdint>

#define NTOK 49
#define CDIM 128
#define HEADS 4
#define HD 32
#define THREADS 768

static constexpr float SCALE = 0.17677669529663687f; // 32^-0.5

typedef unsigned long long ull;
typedef unsigned int u32;
typedef unsigned short u16;

// ---- smem byte offsets ----
#define OFF_AH   0u         // A-fragment tile hi: 64 rows x 128 k bf16 = 16KB
#define OFF_AL   16384u     // A-fragment tile lo: 16KB
#define OFF_QKV  32768u     // fp32 qkv [49][404] = 79184B
#define OFF_MASK 111952u    // 49*49 fp32 = 9604B
#define OFF_P    121568u    // p-scratch [49][196] fp32 = 38416B
#define SMEM_BYTES 160000
#define QKV_STR  404

// ---- device globals: fragment-ordered bf16 hi/lo weights + gathered pos bias ----
__device__ u32 g_wq_hi[48 * 8 * 32 * 2];   // [nt][kc][lane][reg] u32; nt 0-47 (3 chunks x 16)
__device__ u32 g_wq_lo[48 * 8 * 32 * 2];
__device__ u32 g_wp_hi[16 * 8 * 32 * 2];
__device__ u32 g_wp_lo[16 * 8 * 32 * 2];
__device__ float g_pbias[HEADS * NTOK * NTOK];

// ============================ helpers ============================
__device__ __forceinline__ ull pk2(float lo, float hi) {
    ull r; asm("mov.b64 %0, {%1, %2};" : "=l"(r) : "f"(lo), "f"(hi)); return r;
}
__device__ __forceinline__ void upk2(ull v, float& lo, float& hi) {
    asm("mov.b64 {%0, %1}, %2;" : "=f"(lo), "=f"(hi) : "l"(v));
}
__device__ __forceinline__ ull fma2(ull a, ull b, ull c) {
    ull d; asm("fma.rn.f32x2 %0, %1, %2, %3;" : "=l"(d) : "l"(a), "l"(b), "l"(c)); return d;
}
__device__ __forceinline__ u32 bf2(float a, float b) {
    __nv_bfloat162 h = __floats2bfloat162_rn(a, b);
    return *reinterpret_cast<u32*>(&h);
}
// A-fragment u32 index for element pair (row, col) with col even, 64x128 tile
__device__ __forceinline__ int a_idx(int row, int col) {
    int mt = row >> 4, rlo = row & 15, kc = col >> 4, kk = col & 15;
    int l = (rlo & 7) * 4 + ((kk & 7) >> 1);
    int reg = ((rlo >> 3) & 1) + (((kk >> 3) & 1) << 1);
    return ((mt * 8 + kc) * 32 + l) * 4 + reg;
}
__device__ __forceinline__ void mma16816(float c[4], const uint4& a, const uint2& b) {
    asm volatile(
        "mma.sync.aligned.m16n8k16.row.col.f32.bf16.bf16.f32 "
        "{%0,%1,%2,%3}, {%4,%5,%6,%7}, {%8,%9}, {%0,%1,%2,%3};"
        : "+f"(c[0]), "+f"(c[1]), "+f"(c[2]), "+f"(c[3])
        : "r"(a.x), "r"(a.y), "r"(a.z), "r"(a.w), "r"(b.x), "r"(b.y));
}

// ================= prep: weights -> bf16 hi/lo fragment order; pos bias gather =================
__global__ void prep_kernel(const float* __restrict__ qkv_w,
                            const float* __restrict__ proj_w,
                            const float* __restrict__ table,
                            const int*   __restrict__ pidx)
{
    int i = blockIdx.x * 256 + threadIdx.x;
    if (i < 3 * CDIM * CDIM) {
        int o = i / CDIM, c = i % CDIM;
        float w = qkv_w[i];
        __nv_bfloat16 h = __float2bfloat16(w);
        float hf = __bfloat162float(h);
        int nt = o >> 3, g = o & 7, kc = c >> 4, kk = c & 15;
        int l = g * 4 + ((kk & 7) >> 1);
        int reg = (kk >> 3) & 1;
        int u16idx = (((nt * 8 + kc) * 32 + l) * 2 + reg) * 2 + (kk & 1);
        ((u16*)g_wq_hi)[u16idx] = *(u16*)&h;
        __nv_bfloat16 lo = __float2bfloat16(w - hf);
        ((u16*)g_wq_lo)[u16idx] = *(u16*)&lo;
    }
    if (i < CDIM * CDIM) {
        int o = i / CDIM, c = i % CDIM;
        float w = proj_w[i];
        __nv_bfloat16 h = __float2bfloat16(w);
        float hf = __bfloat162float(h);
        int nt = o >> 3, g = o & 7, kc = c >> 4, kk = c & 15;
        int l = g * 4 + ((kk & 7) >> 1);
        int reg = (kk >> 3) & 1;
        int u16idx = (((nt * 8 + kc) * 32 + l) * 2 + reg) * 2 + (kk & 1);
        ((u16*)g_wp_hi)[u16idx] = *(u16*)&h;
        __nv_bfloat16 lo = __float2bfloat16(w - hf);
        ((u16*)g_wp_lo)[u16idx] = *(u16*)&lo;
    }
    if (i < HEADS * NTOK * NTOK) {
        int h = i / (NTOK * NTOK), r = i % (NTOK * NTOK);
        int m = r / NTOK, n = r % NTOK;
        g_pbias[i] = table[pidx[n * NTOK + m] * HEADS + h];
    }
}

// ================================ main kernel ================================
__global__ void __launch_bounds__(THREADS, 1)
win_attn_kernel(const float* __restrict__ x,
                const float* __restrict__ mask,
                const float* __restrict__ proj_b,
                float* __restrict__ out,
                int nW)
{
    extern __shared__ char smem[];
    const int b = blockIdx.x;
    const int t = threadIdx.x;
    const int wid = t >> 5;
    const int lane = t & 31;

    u32* sAh = (u32*)(smem + OFF_AH);
    u32* sAl = (u32*)(smem + OFF_AL);
    float* s_qkv  = (float*)(smem + OFF_QKV);
    float* s_mask = (float*)(smem + OFF_MASK);
    float* s_p    = (float*)(smem + OFF_P);

    // ---- Phase 0: zero A-fragment region (padding rows 49-63 must stay 0) ----
    {
        uint4* z = (uint4*)(smem + OFF_AH);
        #pragma unroll 1
        for (int i = t; i < 2048; i += THREADS)
            z[i] = make_uint4(0, 0, 0, 0);
    }
    __syncthreads();

    // ---- Phase 1: x -> A-fragments (hi/lo); mask -> smem ----
    {
        const float4* x4 = (const float4*)(x + (size_t)b * NTOK * CDIM);
        #pragma unroll 1
        for (int i = t; i < NTOK * CDIM / 4; i += THREADS) {
            float4 v = __ldg(x4 + i);
            int n = i >> 5, c4 = (i & 31) << 2;
            float h0 = __bfloat162float(__float2bfloat16(v.x));
            float h1 = __bfloat162float(__float2bfloat16(v.y));
            float h2 = __bfloat162float(__float2bfloat16(v.z));
            float h3 = __bfloat162float(__float2bfloat16(v.w));
            int i0 = a_idx(n, c4);
            int i1 = i0 + 4;
            sAh[i0] = bf2(v.x, v.y);
            sAh[i1] = bf2(v.z, v.w);
            sAl[i0] = bf2(v.x - h0, v.y - h1);
            sAl[i1] = bf2(v.z - h2, v.w - h3);
        }
        const float* mrow = mask + (size_t)(b % nW) * NTOK * NTOK;
        #pragma unroll 1
        for (int i = t; i < NTOK * NTOK; i += THREADS)
            s_mask[i] = __ldg(mrow + i);
    }
    __syncthreads();

    // ---- GEMM1: qkv = x @ Wqkv^T; 24 warps = 3 chunks x (2 mtg x 4 ng) ----
    {
        const int wchunk = wid >> 3;          // 0..2
        const int sub    = wid & 7;
        const int mtg    = sub >> 2;          // 0..1 -> m-tiles {2mtg, 2mtg+1}
        const int ng     = sub & 3;           // 0..3 -> n-tiles ng*4..ng*4+3

        float C[2][4][4];
        #pragma unroll
        for (int a = 0; a < 2; a++)
            #pragma unroll
            for (int j = 0; j < 4; j++)
                C[a][j][0] = C[a][j][1] = C[a][j][2] = C[a][j][3] = 0.f;

        #pragma unroll
        for (int kc = 0; kc < 8; kc++) {
            uint4 ah0 = *(const uint4*)(sAh + (((2 * mtg)     * 8 + kc) * 32 + lane) * 4);
            uint4 al0 = *(const uint4*)(sAl + (((2 * mtg)     * 8 + kc) * 32 + lane) * 4);
            uint4 ah1 = *(const uint4*)(sAh + (((2 * mtg + 1) * 8 + kc) * 32 + lane) * 4);
            uint4 al1 = *(const uint4*)(sAl + (((2 * mtg + 1) * 8 + kc) * 32 + lane) * 4);
            #pragma unroll
            for (int j = 0; j < 4; j++) {
                int ntg = wchunk * 16 + ng * 4 + j;
                int bidx = ((ntg * 8 + kc) * 32 + lane) * 2;
                uint2 bh = __ldg((const uint2*)(g_wq_hi + bidx));
                uint2 bl = __ldg((const uint2*)(g_wq_lo + bidx));
                mma16816(C[0][j], ah0, bh);
                mma16816(C[0][j], ah0, bl);
                mma16816(C[0][j], al0, bh);
                mma16816(C[1][j], ah1, bh);
                mma16816(C[1][j], ah1, bl);
                mma16816(C[1][j], al1, bh);
            }
        }
        // store C -> s_qkv fp32
        int g = lane >> 2, t4 = lane & 3;
        #pragma unroll
        for (int a = 0; a < 2; a++) {
            int row0 = (2 * mtg + a) * 16 + g;
            #pragma unroll
            for (int j = 0; j < 4; j++) {
                int col = wchunk * 128 + (ng * 4 + j) * 8 + 2 * t4;
                if (row0 < NTOK)
                    *(float2*)(s_qkv + row0 * QKV_STR + col) = make_float2(C[a][j][0], C[a][j][1]);
                if (row0 + 8 < NTOK)
                    *(float2*)(s_qkv + (row0 + 8) * QKV_STR + col) = make_float2(C[a][j][2], C[a][j][3]);
            }
        }
    }
    __syncthreads();

    // ---- Phase 3: scalar attention per (head, row); logits in p-scratch ----
    if (t < HEADS * NTOK) {
        const int hh = t / NTOK;
        const int nn = t % NTOK;

        ull q2[16];
        const ulonglong2* qrow = (const ulonglong2*)(s_qkv + nn * QKV_STR + hh * HD);
        #pragma unroll
        for (int i = 0; i < 8; i++) {
            ulonglong2 v = qrow[i];
            q2[2 * i] = v.x; q2[2 * i + 1] = v.y;
        }
        float mx = -1e30f;
        const float* pbrow = g_pbias + hh * (NTOK * NTOK) + nn;
        const float* mkrow = s_mask + nn * NTOK;
        float* pcol = s_p + t;                 // private column, stride 196

        #pragma unroll
        for (int m = 0; m < NTOK; m++) {
            const ulonglong2* krow =
                (const ulonglong2*)(s_qkv + m * QKV_STR + CDIM + hh * HD);
            ull sa = 0ull, sb = 0ull;
            #pragma unroll
            for (int i = 0; i < 8; i++) {
                ulonglong2 kv = krow[i];
                sa = fma2(q2[2 * i],     kv.x, sa);
                sb = fma2(q2[2 * i + 1], kv.y, sb);
            }
            float a0, a1, b0, b1; upk2(sa, a0, a1); upk2(sb, b0, b1);
            float dot = (a0 + a1) + (b0 + b1);
            float s = fmaf(dot, SCALE, __ldg(pbrow + m * NTOK) + mkrow[m]);
            pcol[m * 196] = s;
            mx = fmaxf(mx, s);
        }
        ull oacc[16];
        #pragma unroll
        for (int i = 0; i < 16; i++) oacc[i] = 0ull;
        float sum = 0.f;
        #pragma unroll
        for (int m = 0; m < NTOK; m++) {
            float e = __expf(pcol[m * 196] - mx);
            sum += e;
            ull e2 = pk2(e, e);
            const ulonglong2* vrow =
                (const ulonglong2*)(s_qkv + m * QKV_STR + 2 * CDIM + hh * HD);
            #pragma unroll
            for (int i = 0; i < 8; i++) {
                ulonglong2 vv = vrow[i];
                oacc[2 * i]     = fma2(e2, vv.x, oacc[2 * i]);
                oacc[2 * i + 1] = fma2(e2, vv.y, oacc[2 * i + 1]);
            }
        }
        float inv = 1.0f / sum;

        // write o -> A-fragments (hi/lo); rows 49-63 keep zeros (x frags are dead:
        // all GEMM1 reads completed before the preceding __syncthreads)
        #pragma unroll
        for (int i = 0; i < 16; i++) {
            float v0, v1; upk2(oacc[i], v0, v1);
            v0 *= inv; v1 *= inv;
            float h0 = __bfloat162float(__float2bfloat16(v0));
            float h1 = __bfloat162float(__float2bfloat16(v1));
            int c = hh * HD + 2 * i;
            int idx = a_idx(nn, c);
            sAh[idx] = bf2(v0, v1);
            sAl[idx] = bf2(v0 - h0, v1 - h1);
        }
    }
    __syncthreads();

    // ---- GEMM2: out = o @ Wproj^T + bias; 8 warps (2 mtg x 4 ng) ----
    if (wid < 8) {
        const int mtg = (wid >> 2) & 1;
        const int ng  = wid & 3;

        float C[2][4][4];
        #pragma unroll
        for (int a = 0; a < 2; a++)
            #pragma unroll
            for (int j = 0; j < 4; j++)
                C[a][j][0] = C[a][j][1] = C[a][j][2] = C[a][j][3] = 0.f;

        #pragma unroll
        for (int kc = 0; kc < 8; kc++) {
            uint4 ah0 = *(const uint4*)(sAh + (((2 * mtg)     * 8 + kc) * 32 + lane) * 4);
            uint4 al0 = *(const uint4*)(sAl + (((2 * mtg)     * 8 + kc) * 32 + lane) * 4);
            uint4 ah1 = *(const uint4*)(sAh + (((2 * mtg + 1) * 8 + kc) * 32 + lane) * 4);
            uint4 al1 = *(const uint4*)(sAl + (((2 * mtg + 1) * 8 + kc) * 32 + lane) * 4);
            #pragma unroll
            for (int j = 0; j < 4; j++) {
                int ntg = ng * 4 + j;
                int bidx = ((ntg * 8 + kc) * 32 + lane) * 2;
                uint2 bh = __ldg((const uint2*)(g_wp_hi + bidx));
                uint2 bl = __ldg((const uint2*)(g_wp_lo + bidx));
                mma16816(C[0][j], ah0, bh);
                mma16816(C[0][j], ah0, bl);
                mma16816(C[0][j], al0, bh);
                mma16816(C[1][j], ah1, bh);
                mma16816(C[1][j], ah1, bl);
                mma16816(C[1][j], al1, bh);
            }
        }
        int g = lane >> 2, t4 = lane & 3;
        float* ob = out + (size_t)b * NTOK * CDIM;
        #pragma unroll
        for (int a = 0; a < 2; a++) {
            int row0 = (2 * mtg + a) * 16 + g;
            #pragma unroll
            for (int j = 0; j < 4; j++) {
                int col = (ng * 4 + j) * 8 + 2 * t4;
                float2 bias = __ldg((const float2*)(proj_b + col));
                if (row0 < NTOK)
                    *(float2*)(ob + row0 * CDIM + col) =
                        make_float2(C[a][j][0] + bias.x, C[a][j][1] + bias.y);
                if (row0 + 8 < NTOK)
                    *(float2*)(ob + (row0 + 8) * CDIM + col) =
                        make_float2(C[a][j][2] + bias.x, C[a][j][3] + bias.y);
            }
        }
    }
}

extern "C" void kernel_launch(void* const* d_in, const int* in_sizes, int n_in,
                              void* d_out, int out_size)
{
    const float* x      = (const float*)d_in[0];
    const float* qkv_w  = (const float*)d_in[1];
    const float* proj_w = (const float*)d_in[2];
    const float* proj_b = (const float*)d_in[3];
    const float* table  = (const float*)d_in[4];
    const float* mask   = (const float*)d_in[5];
    const int*   pidx   = (const int*)d_in[6];
    float* out = (float*)d_out;

    int B  = in_sizes[0] / (NTOK * CDIM);      // 8192
    int nW = in_sizes[5] / (NTOK * NTOK);      // 1024

    prep_kernel<<<(3 * CDIM * CDIM + 255) / 256, 256>>>(qkv_w, proj_w, table, pidx);

    cudaFuncSetAttribute(win_attn_kernel,
                         cudaFuncAttributeMaxDynamicSharedMemorySize, SMEM_BYTES);
    win_attn_kernel<<<B, THREADS, SMEM_BYTES>>>(x, mask, proj_b, out, nW);
}